// round 15
// baseline (speedup 1.0000x reference)
#include <cuda_runtime.h>
#include <math.h>

#define N    4096
#define KK   50
#define LW   64
#define NG   (LW*LW)
#define TS   256           // knn block threads
#define QB   8             // queries per knn block
#define CAP  512           // per-query candidate capacity

// ---------------- scratch (device globals; no allocation allowed) -------------
__device__ int    g_idx[N*KK];
__device__ float  g_nrm[N*3];
__device__ float  g_t1[N*3];
__device__ float  g_t2[N*3];
__device__ float  g_dt[N*KK*2];
__device__ float2 g_coords2[N*KK];
__device__ float  g_maxlen[N];
__device__ float  g_gauss[N];
__device__ double g_contrib[N];

// order-preserving float->uint map (ascending)
__device__ __forceinline__ unsigned fmap(float f) {
    unsigned u = __float_as_uint(f);
    return (u & 0x80000000u) ? ~u : (u | 0x80000000u);
}

// ---------------- stage 1: brute-force KNN, 8 queries per block ---------------
// Same structure/expressions as the R6-exact QB=4 version; only QB and CAP
// changed. Candidate sets and (key,idx) ordering bit-identical -> g_idx
// bit-identical.
__global__ __launch_bounds__(TS) void knn_q8_kernel(const float* __restrict__ pts) {
    __shared__ int                shist[QB][1024];   // 32 KB
    __shared__ unsigned long long slist[QB][CAP];    // 32 KB
    __shared__ int   pa[TS], pb[TS];
    __shared__ int   scnt[QB];
    __shared__ int   sbstar[QB];

    int t = threadIdx.x;
    int i0 = blockIdx.x * QB;

    float qx[QB], qy[QB], qz[QB], qd2[QB];
    #pragma unroll
    for (int q = 0; q < QB; q++) {
        float x = pts[3*(i0+q)+0], y = pts[3*(i0+q)+1], z = pts[3*(i0+q)+2];
        qx[q] = x; qy[q] = y; qz[q] = z;
        qd2[q] = (x*x + y*y) + z*z;                 // EXACT expression
    }

    for (int b = t; b < QB*1024; b += TS) ((int*)shist)[b] = 0;
    if (t < QB) { scnt[t] = 0; sbstar[t] = 1023; }
    __syncthreads();

    // pass 1: histogram
    for (int j = t; j < N; j += TS) {
        float x = pts[3*j+0], y = pts[3*j+1], z = pts[3*j+2];
        float d2j = (x*x + y*y) + z*z;              // EXACT expression
        #pragma unroll
        for (int q = 0; q < QB; q++) {
            float dot = (qx[q]*x + qy[q]*y) + qz[q]*z;
            float sd  = (qd2[q] - 2.0f*dot) + d2j;  // EXACT expression
            atomicAdd(&shist[q][fmap(sd) >> 22], 1);
        }
    }
    __syncthreads();

    // per-query: scan 1024 bins, find rank-50 bin
    for (int q = 0; q < QB; q++) {
        int b0 = t * 4;
        int h0 = shist[q][b0], h1 = shist[q][b0+1], h2 = shist[q][b0+2], h3 = shist[q][b0+3];
        int sum4 = h0 + h1 + h2 + h3;
        pa[t] = sum4;
        __syncthreads();
        int* src = pa; int* dst = pb;
        #pragma unroll
        for (int off = 1; off < TS; off <<= 1) {
            int v = src[t];
            if (t >= off) v += src[t - off];
            dst[t] = v;
            __syncthreads();
            int* tmp = src; src = dst; dst = tmp;
        }
        int run = src[t] - sum4;
        int hh[4] = {h0, h1, h2, h3};
        #pragma unroll
        for (int u = 0; u < 4; u++) {
            int after = run + hh[u];
            if (run < KK && after >= KK) sbstar[q] = b0 + u;
            run = after;
        }
        __syncthreads();
    }
    unsigned bs[QB];
    #pragma unroll
    for (int q = 0; q < QB; q++) bs[q] = (unsigned)sbstar[q];

    // pass 2: recompute + compact candidates
    for (int j = t; j < N; j += TS) {
        float x = pts[3*j+0], y = pts[3*j+1], z = pts[3*j+2];
        float d2j = (x*x + y*y) + z*z;
        #pragma unroll
        for (int q = 0; q < QB; q++) {
            float dot = (qx[q]*x + qy[q]*y) + qz[q]*z;
            float sd  = (qd2[q] - 2.0f*dot) + d2j;
            unsigned key = fmap(sd);
            if ((key >> 22) <= bs[q]) {
                int pos = atomicAdd(&scnt[q], 1);
                if (pos < CAP)
                    slist[q][pos] = ((unsigned long long)key << 32) | (unsigned)j;
            }
        }
    }
    __syncthreads();

    // extraction: 32 threads per query, rank = #{smaller candidates}
    {
        int q  = t >> 5;          // 0..7
        int s  = t & 31;
        int M  = scnt[q] < CAP ? scnt[q] : CAP;
        const unsigned long long* lst = slist[q];
        for (int s0 = s; s0 < M; s0 += 32) {
            unsigned long long mine = lst[s0];
            int rank = 0;
            for (int u = 0; u < M; u++) rank += (lst[u] < mine) ? 1 : 0;
            if (rank < KK)
                g_idx[(i0+q)*KK + rank] = (int)(unsigned)(mine & 0xFFFFFFFFu);
        }
    }
}

// =============== faithful fp32 LAPACK ports (ssyevd path for n=3) =============
__device__ __forceinline__ float slapy2f(float x, float y) {
    float xa = fabsf(x), ya = fabsf(y);
    float w = fmaxf(xa, ya), zz = fminf(xa, ya);
    if (zz == 0.0f) return w;
    float q = zz / w;
    return w * sqrtf(1.0f + q*q);
}

__device__ __forceinline__ void slartgf(float f, float g, float* c, float* s, float* r) {
    if (g == 0.0f)      { *c = 1.0f; *s = 0.0f; *r = f; }
    else if (f == 0.0f) { *c = 0.0f; *s = copysignf(1.0f, g); *r = fabsf(g); }
    else {
        float d = sqrtf(f*f + g*g);
        *c = fabsf(f) / d;
        *r = copysignf(d, f);
        *s = g / (*r);
    }
}

__device__ void slaev2f(float a, float b, float c,
                        float* rt1, float* rt2, float* cs1, float* sn1) {
    float sm  = a + c;
    float df  = a - c;
    float adf = fabsf(df);
    float tb  = b + b;
    float ab  = fabsf(tb);
    float acmx, acmn;
    if (fabsf(a) > fabsf(c)) { acmx = a; acmn = c; }
    else                     { acmx = c; acmn = a; }
    float rt;
    if (adf > ab)      rt = adf * sqrtf(1.0f + (ab/adf)*(ab/adf));
    else if (adf < ab) rt = ab  * sqrtf(1.0f + (adf/ab)*(adf/ab));
    else               rt = ab  * sqrtf(2.0f);
    int sgn1;
    if (sm < 0.0f) {
        *rt1 = 0.5f*(sm - rt); sgn1 = -1;
        *rt2 = (acmx / *rt1)*acmn - (b / *rt1)*b;
    } else if (sm > 0.0f) {
        *rt1 = 0.5f*(sm + rt); sgn1 = 1;
        *rt2 = (acmx / *rt1)*acmn - (b / *rt1)*b;
    } else {
        *rt1 = 0.5f*rt; *rt2 = -0.5f*rt; sgn1 = 1;
    }
    int sgn2;
    float cs;
    if (df >= 0.0f) { cs = df + rt; sgn2 = 1; }
    else            { cs = df - rt; sgn2 = -1; }
    float acs = fabsf(cs);
    if (acs > ab) {
        float ct = -tb / cs;
        *sn1 = 1.0f / sqrtf(1.0f + ct*ct);
        *cs1 = ct * (*sn1);
    } else {
        if (ab == 0.0f) { *cs1 = 1.0f; *sn1 = 0.0f; }
        else {
            float tn = -cs / tb;
            *cs1 = 1.0f / sqrtf(1.0f + tn*tn);
            *sn1 = tn * (*cs1);
        }
    }
    if (sgn1 == sgn2) { float tn = *cs1; *cs1 = -(*sn1); *sn1 = tn; }
}

__device__ void ssteqr3(float* d, float* e, float z[3][3]) {
    const float eps    = 5.9604645e-08f;
    const float eps2   = eps * eps;
    const float safmin = 1.1754944e-38f;
    const int   n = 3;
    const int   nmaxit = n * 30;
    int jtot = 0;
    int l1 = 0, l, m, lsv, lend, lendsv;
    float p, g, r, c, s, f, b, rt1, rt2;

L10:
    if (l1 > n-1) goto L160;
    if (l1 > 0) e[l1-1] = 0.0f;
    for (m = l1; m <= n-2; m++) {
        float tst = fabsf(e[m]);
        if (tst == 0.0f) goto L30;
        if (tst <= (sqrtf(fabsf(d[m])) * sqrtf(fabsf(d[m+1]))) * eps) {
            e[m] = 0.0f; goto L30;
        }
    }
    m = n-1;
L30:
    l = l1; lsv = l; lend = m; lendsv = lend; l1 = m + 1;
    if (lend == l) goto L10;
    {
        float anorm = 0.0f;
        for (int i = l; i <= lend; i++)   anorm = fmaxf(anorm, fabsf(d[i]));
        for (int i = l; i <= lend-1; i++) anorm = fmaxf(anorm, fabsf(e[i]));
        if (anorm == 0.0f) goto L10;
    }
    if (fabsf(d[lend]) < fabsf(d[l])) { lend = lsv; l = lendsv; }
    if (lend > l) {
L40:
        if (l != lend) {
            for (m = l; m <= lend-1; m++) {
                float tst = e[m]*e[m];
                if (tst <= (eps2*fabsf(d[m]))*fabsf(d[m+1]) + safmin) goto L60;
            }
        }
        m = lend;
L60:
        if (m < lend) e[m] = 0.0f;
        p = d[l];
        if (m == l) goto L80;
        if (m == l+1) {
            slaev2f(d[l], e[l], d[l+1], &rt1, &rt2, &c, &s);
            for (int i = 0; i < 3; i++) {
                float tt = z[i][l+1];
                z[i][l+1] = c*tt - s*z[i][l];
                z[i][l]   = s*tt + c*z[i][l];
            }
            d[l] = rt1; d[l+1] = rt2; e[l] = 0.0f;
            l += 2;
            if (l <= lend) goto L40;
            goto L140;
        }
        if (jtot == nmaxit) goto L140;
        jtot++;
        g = (d[l+1] - p) / (2.0f * e[l]);
        r = slapy2f(g, 1.0f);
        g = d[m] - p + e[l] / (g + copysignf(r, g));
        s = 1.0f; c = 1.0f; p = 0.0f;
        {
            float carr[2], sarr[2];
            for (int i = m-1; i >= l; i--) {
                f = s * e[i]; b = c * e[i];
                slartgf(g, f, &c, &s, &r);
                if (i != m-1) e[i+1] = r;
                g = d[i+1] - p;
                r = (d[i] - g)*s + 2.0f*c*b;
                p = s * r;
                d[i+1] = g + p;
                g = c*r - b;
                carr[i-l] = c; sarr[i-l] = -s;
            }
            int nrot = m - l;
            for (int j = nrot-1; j >= 0; j--) {
                float ct = carr[j], st = sarr[j];
                for (int i = 0; i < 3; i++) {
                    float tt = z[i][l+j+1];
                    z[i][l+j+1] = ct*tt - st*z[i][l+j];
                    z[i][l+j]   = st*tt + ct*z[i][l+j];
                }
            }
        }
        d[l] = d[l] - p;
        e[l] = g;
        goto L40;
L80:
        d[l] = p;
        l++;
        if (l <= lend) goto L40;
        goto L140;
    } else {
L90:
        if (l != lend) {
            for (m = l; m >= lend+1; m--) {
                float tst = e[m-1]*e[m-1];
                if (tst <= (eps2*fabsf(d[m]))*fabsf(d[m-1]) + safmin) goto L110;
            }
        }
        m = lend;
L110:
        if (m > lend) e[m-1] = 0.0f;
        p = d[l];
        if (m == l) goto L130;
        if (m == l-1) {
            slaev2f(d[l-1], e[l-1], d[l], &rt1, &rt2, &c, &s);
            for (int i = 0; i < 3; i++) {
                float tt = z[i][l];
                z[i][l]   = c*tt - s*z[i][l-1];
                z[i][l-1] = s*tt + c*z[i][l-1];
            }
            d[l-1] = rt1; d[l] = rt2; e[l-1] = 0.0f;
            l -= 2;
            if (l >= lend) goto L90;
            goto L140;
        }
        if (jtot == nmaxit) goto L140;
        jtot++;
        g = (d[l-1] - p) / (2.0f * e[l-1]);
        r = slapy2f(g, 1.0f);
        g = d[m] - p + e[l-1] / (g + copysignf(r, g));
        s = 1.0f; c = 1.0f; p = 0.0f;
        {
            float carr[2], sarr[2];
            for (int i = m; i <= l-1; i++) {
                f = s * e[i]; b = c * e[i];
                slartgf(g, f, &c, &s, &r);
                if (i != m) e[i-1] = r;
                g = d[i] - p;
                r = (d[i+1] - g)*s + 2.0f*c*b;
                p = s * r;
                d[i] = g + p;
                g = c*r - b;
                carr[i-m] = c; sarr[i-m] = s;
            }
            int nrot = l - m;
            for (int j = 0; j <= nrot-1; j++) {
                float ct = carr[j], st = sarr[j];
                for (int i = 0; i < 3; i++) {
                    float tt = z[i][m+j+1];
                    z[i][m+j+1] = ct*tt - st*z[i][m+j];
                    z[i][m+j]   = st*tt + ct*z[i][m+j];
                }
            }
        }
        d[l] = d[l] - p;
        e[l-1] = g;
        goto L90;
L130:
        d[l] = p;
        l--;
        if (l >= lend) goto L90;
        goto L140;
    }
L140:
    if (jtot < nmaxit) goto L10;
L160:
    for (int ii = 1; ii <= n-1; ii++) {
        int i = ii - 1, k = i;
        p = d[i];
        for (int j = ii; j <= n-1; j++) {
            if (d[j] < p) { k = j; p = d[j]; }
        }
        if (k != i) {
            d[k] = d[i]; d[i] = p;
            for (int row = 0; row < 3; row++) {
                float tt = z[row][i]; z[row][i] = z[row][k]; z[row][k] = tt;
            }
        }
    }
}

__device__ void ssyevd3(float a11, float a21, float a31,
                        float a22, float a32, float a33,
                        float* d, float z[3][3]) {
    float alpha = a21;
    float xnorm = fabsf(a31);
    float beta, taui, v2;
    if (xnorm == 0.0f) { taui = 0.0f; beta = alpha; v2 = 0.0f; }
    else {
        beta = -copysignf(slapy2f(alpha, xnorm), alpha);
        taui = (beta - alpha) / beta;
        v2   = a31 / (alpha - beta);
    }
    float e[2];
    e[0] = beta;
    if (taui != 0.0f) {
        float w1 = taui * (a22*1.0f + a32*v2);
        float w2 = taui * (a32*1.0f + a33*v2);
        float al = -0.5f * taui * (w1*1.0f + w2*v2);
        w1 = w1 + al*1.0f;
        w2 = w2 + al*v2;
        a22 = a22 - (1.0f*w1 + w1*1.0f);
        a32 = a32 - (v2*w1 + w2*1.0f);
        a33 = a33 - (v2*w2 + w2*v2);
    }
    d[0] = a11; d[1] = a22; d[2] = a33;
    e[1] = a32;
    z[0][0] = 1.0f; z[0][1] = 0.0f; z[0][2] = 0.0f;
    z[1][0] = 0.0f; z[2][0] = 0.0f;
    z[1][1] = 1.0f - taui;
    z[1][2] = -taui * v2;
    z[2][1] = -taui * v2;
    z[2][2] = 1.0f - (taui * v2) * v2;
    ssteqr3(d, e, z);
}

// ---------------- stage 2: frames + tangent coords + bbox (R9 staged) --------
__global__ __launch_bounds__(32) void frames_kernel(const float* __restrict__ pts) {
    __shared__ float sp[KK*3*32];                 // 19.2 KB
    int t = threadIdx.x;
    int i = blockIdx.x * 32 + t;
    const int* idx = g_idx + i*KK;

    #pragma unroll
    for (int r = 0; r < KK; r++) {
        int j = idx[r];
        sp[(3*r+0)*32 + t] = pts[3*j+0];
        sp[(3*r+1)*32 + t] = pts[3*j+1];
        sp[(3*r+2)*32 + t] = pts[3*j+2];
    }

    float mx = 0.f, my = 0.f, mz = 0.f;
    for (int r = 0; r < KK; r++) {
        mx += sp[(3*r+0)*32 + t];
        my += sp[(3*r+1)*32 + t];
        mz += sp[(3*r+2)*32 + t];
    }
    mx /= 50.0f; my /= 50.0f; mz /= 50.0f;
    float A00=0.f, A01=0.f, A02=0.f, A11=0.f, A12=0.f, A22=0.f;
    for (int r = 0; r < KK; r++) {
        float cx = sp[(3*r+0)*32 + t]-mx;
        float cy = sp[(3*r+1)*32 + t]-my;
        float cz = sp[(3*r+2)*32 + t]-mz;
        A00 += cx*cx; A01 += cx*cy; A02 += cx*cz;
        A11 += cy*cy; A12 += cy*cz; A22 += cz*cz;
    }
    A00*=0.5f; A01*=0.5f; A02*=0.5f; A11*=0.5f; A12*=0.5f; A22*=0.5f;

    float d[3];
    float V[3][3];
    ssyevd3(A00, A01, A02, A11, A12, A22, d, V);

    float nx  = V[0][0], ny  = V[1][0], nz  = V[2][0];
    float t1x = V[0][1], t1y = V[1][1], t1z = V[2][1];
    float t2x = V[0][2], t2y = V[1][2], t2z = V[2][2];
    float det = nx*(t1y*t2z - t1z*t2y)
              - ny*(t1x*t2z - t1z*t2x)
              + nz*(t1x*t2y - t1y*t2x);
    t1x *= det; t1y *= det; t1z *= det;
    g_nrm[3*i+0]=nx;  g_nrm[3*i+1]=ny;  g_nrm[3*i+2]=nz;
    g_t1 [3*i+0]=t1x; g_t1 [3*i+1]=t1y; g_t1 [3*i+2]=t1z;
    g_t2 [3*i+0]=t2x; g_t2 [3*i+1]=t2y; g_t2 [3*i+2]=t2z;
    float px = pts[3*i+0], py = pts[3*i+1], pz = pts[3*i+2];
    float bminx = INFINITY, bminy = INFINITY, bmaxx = -INFINITY, bmaxy = -INFINITY;
    for (int r = 0; r < KK; r++) {
        float dx = sp[(3*r+0)*32 + t]-px;
        float dy = sp[(3*r+1)*32 + t]-py;
        float dz = sp[(3*r+2)*32 + t]-pz;
        float a0 = (dx*t1x + dy*t1y) + dz*t1z;
        float a1 = (dx*t2x + dy*t2y) + dz*t2z;
        g_dt[(i*KK+r)*2+0] = a0;
        g_dt[(i*KK+r)*2+1] = a1;
        bminx = fminf(bminx, a0); bmaxx = fmaxf(bmaxx, a0);
        bminy = fminf(bminy, a1); bmaxy = fmaxf(bmaxy, a1);
    }
    bminx *= 1.1f; bminy *= 1.1f; bmaxx *= 1.1f; bmaxy *= 1.1f;
    float ml = fmaxf(bmaxx - bminx, bmaxy - bminy);
    g_maxlen[i] = ml;
    for (int r = 0; r < KK; r++) {
        float a0 = g_dt[(i*KK+r)*2+0];
        float a1 = g_dt[(i*KK+r)*2+1];
        float c0 = (a0 - bminx)/ml*2.0f - 1.0f;
        float c1 = (a1 - bminy)/ml*2.0f - 1.0f;
        g_coords2[i*KK+r] = make_float2(c0, c1);
    }
}

// ---------------- stage 3: shape operator + gaussian curvature (R9 staged) ----
__global__ __launch_bounds__(32) void gauss_kernel() {
    __shared__ float sn[KK*3*32];                 // 19.2 KB
    int t = threadIdx.x;
    int i = blockIdx.x * 32 + t;
    const int* idx = g_idx + i*KK;

    #pragma unroll
    for (int r = 0; r < KK; r++) {
        int j = idx[r];
        sn[(3*r+0)*32 + t] = g_nrm[3*j+0];
        sn[(3*r+1)*32 + t] = g_nrm[3*j+1];
        sn[(3*r+2)*32 + t] = g_nrm[3*j+2];
    }

    float n0x = g_nrm[3*i+0], n0y = g_nrm[3*i+1], n0z = g_nrm[3*i+2];
    float t1x = g_t1[3*i+0],  t1y = g_t1[3*i+1],  t1z = g_t1[3*i+2];
    float t2x = g_t2[3*i+0],  t2y = g_t2[3*i+1],  t2z = g_t2[3*i+2];
    float xx=0.f, xy=0.f, yy=0.f;
    float y00=0.f, y01=0.f, y10=0.f, y11=0.f;
    for (int r = 0; r < KK; r++) {
        float lnx = sn[(3*r+0)*32 + t] - n0x;
        float lny = sn[(3*r+1)*32 + t] - n0y;
        float lnz = sn[(3*r+2)*32 + t] - n0z;
        float dn0 = (lnx*t1x + lny*t1y) + lnz*t1z;
        float dn1 = (lnx*t2x + lny*t2y) + lnz*t2z;
        float dt0 = g_dt[(i*KK+r)*2+0];
        float dt1 = g_dt[(i*KK+r)*2+1];
        xx += dt0*dt0; xy += dt0*dt1; yy += dt1*dt1;
        y00 += dn0*dt0; y01 += dn0*dt1;
        y10 += dn1*dt0; y11 += dn1*dt1;
    }
    float S00 = y00 + y00, S01 = y01 + y10, S11 = y11 + y11;
    float tr = xx + yy, df = xx - yy;
    float disc = sqrtf(df*df + 4.0f*xy*xy);
    float a = 0.5f*(tr - disc), b = 0.5f*(tr + disc);
    float vx = xy, vy = b - xx;
    float nn = sqrtf(vx*vx + vy*vy);
    if (nn > 0.0f) { vx /= nn; vy /= nn; }
    else           { vx = 1.0f; vy = 0.0f; }
    float q00 = vy, q10 = -vx, q01 = vx, q11 = vy;
    float sq00 = S00*q00 + S01*q10, sq01 = S00*q01 + S01*q11;
    float sq10 = S01*q00 + S11*q10, sq11 = S01*q01 + S11*q11;
    float m00 = q00*sq00 + q10*sq10;
    float m01 = q00*sq01 + q10*sq11;
    float m10 = q01*sq00 + q11*sq10;
    float m11 = q01*sq01 + q11*sq11;
    float E00 = m00 / (2.0f*a  + 1e-8f);
    float E01 = m01 / ((a + b) + 1e-8f);
    float E10 = m10 / ((a + b) + 1e-8f);
    float E11 = m11 / (2.0f*b  + 1e-8f);
    float u00 = q00*E00 + q01*E10, u01 = q00*E01 + q01*E11;
    float u10 = q10*E00 + q11*E10, u11 = q10*E01 + q11*E11;
    float w00 = u00*q00 + u01*q01;
    float w01 = u00*q10 + u01*q11;
    float w10 = u10*q00 + u11*q01;
    float w11 = u10*q10 + u11*q11;
    g_gauss[i] = w00*w11 - w01*w10;
}

// ---------------- stage 4: Voronoi (R14: R6 body + sure-lose tile gate) ------
// Thread 0 additionally folds this point's contribution (counts * area *
// gauss) using the IDENTICAL float expressions final_kernel used before ->
// final's per-thread accumulation sees identical values in identical order.
__global__ __launch_bounds__(128) void voronoi_kernel() {
    __shared__ float2 ss[KK];
    __shared__ int    sbeat[64];      // -1 = whole tile provably lost, else jstar
    __shared__ int    part[128];
    int i = blockIdx.x;
    int t = threadIdx.x;
    if (t < KK) ss[t] = g_coords2[i*KK + t];
    __syncthreads();
    const float step = 2.0f / 63.0f;

    if (t < 64) {
        int ta = t >> 3, tb = t & 7;
        float cx = -1.0f + ((float)(ta*8) + 3.5f) * step;
        float cy = -1.0f + ((float)(tb*8) + 3.5f) * step;
        float bestd = INFINITY; int bestj = 1;
        for (int j = 1; j < KK; j++) {
            float ex = cx - ss[j].x, ey = cy - ss[j].y;
            float dj = ex*ex + ey*ey;
            if (dj < bestd) { bestd = dj; bestj = j; }
        }
        float e0x = cx - ss[0].x, e0y = cy - ss[0].y;
        float d0c = e0x*e0x + e0y*e0y;
        const float rr = 4.9497475f * step;   // 8x8 tile half-diagonal
        bool sure = (sqrtf(bestd) + 2.0f*rr + 2e-3f) < sqrtf(d0c);
        sbeat[t] = sure ? -1 : bestj;
    }
    __syncthreads();

    float s0x = ss[0].x, s0y = ss[0].y;
    int cnt = 0;
    for (int c = t; c < NG; c += 128) {
        int a = c >> 6, b = c & 63;
        int jstar = sbeat[(a >> 3)*8 + (b >> 3)];
        if (jstar < 0) continue;              // whole tile provably lost
        float gx = -1.0f + (float)a * step;
        float gy = -1.0f + (float)b * step;
        float dx = gx - s0x, dy = gy - s0y;
        float d0 = dx*dx + dy*dy;
        float2 sj = ss[jstar];
        float ex = gx - sj.x, ey = gy - sj.y;
        float djs = ex*ex + ey*ey;
        bool lost = djs < d0;
        if (!lost) {
            for (int j = 1; j < KK; j++) {
                float2 s = ss[j];
                float fx = gx - s.x, fy = gy - s.y;
                float dj = fx*fx + fy*fy;
                if (dj < d0) { lost = true; break; }
            }
        }
        cnt += lost ? 0 : 1;
    }
    part[t] = cnt;
    __syncthreads();
    for (int s = 64; s > 0; s >>= 1) {
        if (t < s) part[t] += part[t+s];
        __syncthreads();
    }
    if (t == 0) {
        float ml = g_maxlen[i];
        float area = (float)part[0] * (ml*ml) / 3969.0f;   // EXACT final expr
        g_contrib[i] = (double)(g_gauss[i] * area);        // EXACT final expr
    }
}

// ---------------- stage 5: final reduction (contrib pre-folded) ---------------
// Per-thread accumulation order identical to the previous final_kernel (same
// i = t, t+1024, ... order over identical double values) -> bit-identical.
__global__ __launch_bounds__(1024) void final_kernel(float* __restrict__ out) {
    __shared__ double sh[1024];
    int t = threadIdx.x;
    double acc = 0.0;
    for (int i = t; i < N; i += 1024) {
        acc += g_contrib[i];
    }
    sh[t] = acc;
    __syncthreads();
    for (int s = 512; s > 0; s >>= 1) {
        if (t < s) sh[t] += sh[t+s];
        __syncthreads();
    }
    if (t == 0) {
        float v = (float)sh[0];
        v = v / 2.0f;
        v = v / 3.14159274101257324f;
        out[0] = v;
    }
}

// ---------------- launch ------------------------------------------------------
extern "C" void kernel_launch(void* const* d_in, const int* in_sizes, int n_in,
                              void* d_out, int out_size) {
    const float* pts = (const float*)d_in[0];
    float* out = (float*)d_out;
    knn_q8_kernel<<<N/QB, TS>>>(pts);
    frames_kernel<<<N/32, 32>>>(pts);
    gauss_kernel <<<N/32, 32>>>();
    voronoi_kernel<<<N, 128>>>();
    final_kernel <<<1, 1024>>>(out);
}

// round 16
// speedup vs baseline: 1.0862x; 1.0862x over previous
#include <cuda_runtime.h>
#include <math.h>

#define N    4096
#define KK   50
#define LW   64
#define NG   (LW*LW)
#define TS   256           // knn block threads
#define QB   4             // queries per knn block
#define CAP  1024          // per-query candidate capacity

// ---------------- scratch (device globals; no allocation allowed) -------------
__device__ int    g_idx[N*KK];
__device__ float  g_nrm[N*3];
__device__ float  g_t1[N*3];
__device__ float  g_t2[N*3];
__device__ float  g_dt[N*KK*2];
__device__ float2 g_coords2[N*KK];
__device__ float  g_maxlen[N];
__device__ float  g_gauss[N];
__device__ double g_contrib[N];

// order-preserving float->uint map (ascending)
__device__ __forceinline__ unsigned fmap(float f) {
    unsigned u = __float_as_uint(f);
    return (u & 0x80000000u) ? ~u : (u | 0x80000000u);
}

// ---------------- stage 1: brute-force KNN, 4 queries per block (R6 exact) ----
__global__ __launch_bounds__(TS) void knn_q4_kernel(const float* __restrict__ pts) {
    __shared__ int                shist[QB][1024];   // 16 KB
    __shared__ unsigned long long slist[QB][CAP];    // 32 KB
    __shared__ int   pa[TS], pb[TS];
    __shared__ int   scnt[QB];
    __shared__ int   sbstar[QB];

    int t = threadIdx.x;
    int i0 = blockIdx.x * QB;

    float qx[QB], qy[QB], qz[QB], qd2[QB];
    #pragma unroll
    for (int q = 0; q < QB; q++) {
        float x = pts[3*(i0+q)+0], y = pts[3*(i0+q)+1], z = pts[3*(i0+q)+2];
        qx[q] = x; qy[q] = y; qz[q] = z;
        qd2[q] = (x*x + y*y) + z*z;                 // EXACT expression
    }

    for (int b = t; b < QB*1024; b += TS) ((int*)shist)[b] = 0;
    if (t < QB) { scnt[t] = 0; sbstar[t] = 1023; }
    __syncthreads();

    // pass 1: histogram
    for (int j = t; j < N; j += TS) {
        float x = pts[3*j+0], y = pts[3*j+1], z = pts[3*j+2];
        float d2j = (x*x + y*y) + z*z;              // EXACT expression
        #pragma unroll
        for (int q = 0; q < QB; q++) {
            float dot = (qx[q]*x + qy[q]*y) + qz[q]*z;
            float sd  = (qd2[q] - 2.0f*dot) + d2j;  // EXACT expression
            atomicAdd(&shist[q][fmap(sd) >> 22], 1);
        }
    }
    __syncthreads();

    // per-query: scan 1024 bins, find rank-50 bin
    for (int q = 0; q < QB; q++) {
        int b0 = t * 4;
        int h0 = shist[q][b0], h1 = shist[q][b0+1], h2 = shist[q][b0+2], h3 = shist[q][b0+3];
        int sum4 = h0 + h1 + h2 + h3;
        pa[t] = sum4;
        __syncthreads();
        int* src = pa; int* dst = pb;
        #pragma unroll
        for (int off = 1; off < TS; off <<= 1) {
            int v = src[t];
            if (t >= off) v += src[t - off];
            dst[t] = v;
            __syncthreads();
            int* tmp = src; src = dst; dst = tmp;
        }
        int run = src[t] - sum4;
        int hh[4] = {h0, h1, h2, h3};
        #pragma unroll
        for (int u = 0; u < 4; u++) {
            int after = run + hh[u];
            if (run < KK && after >= KK) sbstar[q] = b0 + u;
            run = after;
        }
        __syncthreads();
    }
    unsigned bs0 = (unsigned)sbstar[0], bs1 = (unsigned)sbstar[1];
    unsigned bs2 = (unsigned)sbstar[2], bs3 = (unsigned)sbstar[3];

    // pass 2: recompute + compact candidates
    for (int j = t; j < N; j += TS) {
        float x = pts[3*j+0], y = pts[3*j+1], z = pts[3*j+2];
        float d2j = (x*x + y*y) + z*z;
        unsigned bb[QB] = {bs0, bs1, bs2, bs3};
        #pragma unroll
        for (int q = 0; q < QB; q++) {
            float dot = (qx[q]*x + qy[q]*y) + qz[q]*z;
            float sd  = (qd2[q] - 2.0f*dot) + d2j;
            unsigned key = fmap(sd);
            if ((key >> 22) <= bb[q]) {
                int pos = atomicAdd(&scnt[q], 1);
                if (pos < CAP)
                    slist[q][pos] = ((unsigned long long)key << 32) | (unsigned)j;
            }
        }
    }
    __syncthreads();

    // extraction: 64 threads per query, rank = #{smaller candidates}
    {
        int q  = t >> 6;          // 0..3
        int s  = t & 63;
        int M  = scnt[q] < CAP ? scnt[q] : CAP;
        const unsigned long long* lst = slist[q];
        for (int s0 = s; s0 < M; s0 += 64) {
            unsigned long long mine = lst[s0];
            int rank = 0;
            for (int u = 0; u < M; u++) rank += (lst[u] < mine) ? 1 : 0;
            if (rank < KK)
                g_idx[(i0+q)*KK + rank] = (int)(unsigned)(mine & 0xFFFFFFFFu);
        }
    }
}

// =============== faithful fp32 LAPACK ports (ssyevd path for n=3) =============
__device__ __forceinline__ float slapy2f(float x, float y) {
    float xa = fabsf(x), ya = fabsf(y);
    float w = fmaxf(xa, ya), zz = fminf(xa, ya);
    if (zz == 0.0f) return w;
    float q = zz / w;
    return w * sqrtf(1.0f + q*q);
}

__device__ __forceinline__ void slartgf(float f, float g, float* c, float* s, float* r) {
    if (g == 0.0f)      { *c = 1.0f; *s = 0.0f; *r = f; }
    else if (f == 0.0f) { *c = 0.0f; *s = copysignf(1.0f, g); *r = fabsf(g); }
    else {
        float d = sqrtf(f*f + g*g);
        *c = fabsf(f) / d;
        *r = copysignf(d, f);
        *s = g / (*r);
    }
}

__device__ void slaev2f(float a, float b, float c,
                        float* rt1, float* rt2, float* cs1, float* sn1) {
    float sm  = a + c;
    float df  = a - c;
    float adf = fabsf(df);
    float tb  = b + b;
    float ab  = fabsf(tb);
    float acmx, acmn;
    if (fabsf(a) > fabsf(c)) { acmx = a; acmn = c; }
    else                     { acmx = c; acmn = a; }
    float rt;
    if (adf > ab)      rt = adf * sqrtf(1.0f + (ab/adf)*(ab/adf));
    else if (adf < ab) rt = ab  * sqrtf(1.0f + (adf/ab)*(adf/ab));
    else               rt = ab  * sqrtf(2.0f);
    int sgn1;
    if (sm < 0.0f) {
        *rt1 = 0.5f*(sm - rt); sgn1 = -1;
        *rt2 = (acmx / *rt1)*acmn - (b / *rt1)*b;
    } else if (sm > 0.0f) {
        *rt1 = 0.5f*(sm + rt); sgn1 = 1;
        *rt2 = (acmx / *rt1)*acmn - (b / *rt1)*b;
    } else {
        *rt1 = 0.5f*rt; *rt2 = -0.5f*rt; sgn1 = 1;
    }
    int sgn2;
    float cs;
    if (df >= 0.0f) { cs = df + rt; sgn2 = 1; }
    else            { cs = df - rt; sgn2 = -1; }
    float acs = fabsf(cs);
    if (acs > ab) {
        float ct = -tb / cs;
        *sn1 = 1.0f / sqrtf(1.0f + ct*ct);
        *cs1 = ct * (*sn1);
    } else {
        if (ab == 0.0f) { *cs1 = 1.0f; *sn1 = 0.0f; }
        else {
            float tn = -cs / tb;
            *cs1 = 1.0f / sqrtf(1.0f + tn*tn);
            *sn1 = tn * (*cs1);
        }
    }
    if (sgn1 == sgn2) { float tn = *cs1; *cs1 = -(*sn1); *sn1 = tn; }
}

__device__ void ssteqr3(float* d, float* e, float z[3][3]) {
    const float eps    = 5.9604645e-08f;
    const float eps2   = eps * eps;
    const float safmin = 1.1754944e-38f;
    const int   n = 3;
    const int   nmaxit = n * 30;
    int jtot = 0;
    int l1 = 0, l, m, lsv, lend, lendsv;
    float p, g, r, c, s, f, b, rt1, rt2;

L10:
    if (l1 > n-1) goto L160;
    if (l1 > 0) e[l1-1] = 0.0f;
    for (m = l1; m <= n-2; m++) {
        float tst = fabsf(e[m]);
        if (tst == 0.0f) goto L30;
        if (tst <= (sqrtf(fabsf(d[m])) * sqrtf(fabsf(d[m+1]))) * eps) {
            e[m] = 0.0f; goto L30;
        }
    }
    m = n-1;
L30:
    l = l1; lsv = l; lend = m; lendsv = lend; l1 = m + 1;
    if (lend == l) goto L10;
    {
        float anorm = 0.0f;
        for (int i = l; i <= lend; i++)   anorm = fmaxf(anorm, fabsf(d[i]));
        for (int i = l; i <= lend-1; i++) anorm = fmaxf(anorm, fabsf(e[i]));
        if (anorm == 0.0f) goto L10;
    }
    if (fabsf(d[lend]) < fabsf(d[l])) { lend = lsv; l = lendsv; }
    if (lend > l) {
L40:
        if (l != lend) {
            for (m = l; m <= lend-1; m++) {
                float tst = e[m]*e[m];
                if (tst <= (eps2*fabsf(d[m]))*fabsf(d[m+1]) + safmin) goto L60;
            }
        }
        m = lend;
L60:
        if (m < lend) e[m] = 0.0f;
        p = d[l];
        if (m == l) goto L80;
        if (m == l+1) {
            slaev2f(d[l], e[l], d[l+1], &rt1, &rt2, &c, &s);
            for (int i = 0; i < 3; i++) {
                float tt = z[i][l+1];
                z[i][l+1] = c*tt - s*z[i][l];
                z[i][l]   = s*tt + c*z[i][l];
            }
            d[l] = rt1; d[l+1] = rt2; e[l] = 0.0f;
            l += 2;
            if (l <= lend) goto L40;
            goto L140;
        }
        if (jtot == nmaxit) goto L140;
        jtot++;
        g = (d[l+1] - p) / (2.0f * e[l]);
        r = slapy2f(g, 1.0f);
        g = d[m] - p + e[l] / (g + copysignf(r, g));
        s = 1.0f; c = 1.0f; p = 0.0f;
        {
            float carr[2], sarr[2];
            for (int i = m-1; i >= l; i--) {
                f = s * e[i]; b = c * e[i];
                slartgf(g, f, &c, &s, &r);
                if (i != m-1) e[i+1] = r;
                g = d[i+1] - p;
                r = (d[i] - g)*s + 2.0f*c*b;
                p = s * r;
                d[i+1] = g + p;
                g = c*r - b;
                carr[i-l] = c; sarr[i-l] = -s;
            }
            int nrot = m - l;
            for (int j = nrot-1; j >= 0; j--) {
                float ct = carr[j], st = sarr[j];
                for (int i = 0; i < 3; i++) {
                    float tt = z[i][l+j+1];
                    z[i][l+j+1] = ct*tt - st*z[i][l+j];
                    z[i][l+j]   = st*tt + ct*z[i][l+j];
                }
            }
        }
        d[l] = d[l] - p;
        e[l] = g;
        goto L40;
L80:
        d[l] = p;
        l++;
        if (l <= lend) goto L40;
        goto L140;
    } else {
L90:
        if (l != lend) {
            for (m = l; m >= lend+1; m--) {
                float tst = e[m-1]*e[m-1];
                if (tst <= (eps2*fabsf(d[m]))*fabsf(d[m-1]) + safmin) goto L110;
            }
        }
        m = lend;
L110:
        if (m > lend) e[m-1] = 0.0f;
        p = d[l];
        if (m == l) goto L130;
        if (m == l-1) {
            slaev2f(d[l-1], e[l-1], d[l], &rt1, &rt2, &c, &s);
            for (int i = 0; i < 3; i++) {
                float tt = z[i][l];
                z[i][l]   = c*tt - s*z[i][l-1];
                z[i][l-1] = s*tt + c*z[i][l-1];
            }
            d[l-1] = rt1; d[l] = rt2; e[l-1] = 0.0f;
            l -= 2;
            if (l >= lend) goto L90;
            goto L140;
        }
        if (jtot == nmaxit) goto L140;
        jtot++;
        g = (d[l-1] - p) / (2.0f * e[l-1]);
        r = slapy2f(g, 1.0f);
        g = d[m] - p + e[l-1] / (g + copysignf(r, g));
        s = 1.0f; c = 1.0f; p = 0.0f;
        {
            float carr[2], sarr[2];
            for (int i = m; i <= l-1; i++) {
                f = s * e[i]; b = c * e[i];
                slartgf(g, f, &c, &s, &r);
                if (i != m) e[i-1] = r;
                g = d[i] - p;
                r = (d[i+1] - g)*s + 2.0f*c*b;
                p = s * r;
                d[i] = g + p;
                g = c*r - b;
                carr[i-m] = c; sarr[i-m] = s;
            }
            int nrot = l - m;
            for (int j = 0; j <= nrot-1; j++) {
                float ct = carr[j], st = sarr[j];
                for (int i = 0; i < 3; i++) {
                    float tt = z[i][m+j+1];
                    z[i][m+j+1] = ct*tt - st*z[i][m+j];
                    z[i][m+j]   = st*tt + ct*z[i][m+j];
                }
            }
        }
        d[l] = d[l] - p;
        e[l-1] = g;
        goto L90;
L130:
        d[l] = p;
        l--;
        if (l >= lend) goto L90;
        goto L140;
    }
L140:
    if (jtot < nmaxit) goto L10;
L160:
    for (int ii = 1; ii <= n-1; ii++) {
        int i = ii - 1, k = i;
        p = d[i];
        for (int j = ii; j <= n-1; j++) {
            if (d[j] < p) { k = j; p = d[j]; }
        }
        if (k != i) {
            d[k] = d[i]; d[i] = p;
            for (int row = 0; row < 3; row++) {
                float tt = z[row][i]; z[row][i] = z[row][k]; z[row][k] = tt;
            }
        }
    }
}

__device__ void ssyevd3(float a11, float a21, float a31,
                        float a22, float a32, float a33,
                        float* d, float z[3][3]) {
    float alpha = a21;
    float xnorm = fabsf(a31);
    float beta, taui, v2;
    if (xnorm == 0.0f) { taui = 0.0f; beta = alpha; v2 = 0.0f; }
    else {
        beta = -copysignf(slapy2f(alpha, xnorm), alpha);
        taui = (beta - alpha) / beta;
        v2   = a31 / (alpha - beta);
    }
    float e[2];
    e[0] = beta;
    if (taui != 0.0f) {
        float w1 = taui * (a22*1.0f + a32*v2);
        float w2 = taui * (a32*1.0f + a33*v2);
        float al = -0.5f * taui * (w1*1.0f + w2*v2);
        w1 = w1 + al*1.0f;
        w2 = w2 + al*v2;
        a22 = a22 - (1.0f*w1 + w1*1.0f);
        a32 = a32 - (v2*w1 + w2*1.0f);
        a33 = a33 - (v2*w2 + w2*v2);
    }
    d[0] = a11; d[1] = a22; d[2] = a33;
    e[1] = a32;
    z[0][0] = 1.0f; z[0][1] = 0.0f; z[0][2] = 0.0f;
    z[1][0] = 0.0f; z[2][0] = 0.0f;
    z[1][1] = 1.0f - taui;
    z[1][2] = -taui * v2;
    z[2][1] = -taui * v2;
    z[2][2] = 1.0f - (taui * v2) * v2;
    ssteqr3(d, e, z);
}

// ---------------- stage 2: frames + tangent coords + bbox (R9 staged) --------
__global__ __launch_bounds__(32) void frames_kernel(const float* __restrict__ pts) {
    __shared__ float sp[KK*3*32];                 // 19.2 KB
    int t = threadIdx.x;
    int i = blockIdx.x * 32 + t;
    const int* idx = g_idx + i*KK;

    #pragma unroll
    for (int r = 0; r < KK; r++) {
        int j = idx[r];
        sp[(3*r+0)*32 + t] = pts[3*j+0];
        sp[(3*r+1)*32 + t] = pts[3*j+1];
        sp[(3*r+2)*32 + t] = pts[3*j+2];
    }

    float mx = 0.f, my = 0.f, mz = 0.f;
    for (int r = 0; r < KK; r++) {
        mx += sp[(3*r+0)*32 + t];
        my += sp[(3*r+1)*32 + t];
        mz += sp[(3*r+2)*32 + t];
    }
    mx /= 50.0f; my /= 50.0f; mz /= 50.0f;
    float A00=0.f, A01=0.f, A02=0.f, A11=0.f, A12=0.f, A22=0.f;
    for (int r = 0; r < KK; r++) {
        float cx = sp[(3*r+0)*32 + t]-mx;
        float cy = sp[(3*r+1)*32 + t]-my;
        float cz = sp[(3*r+2)*32 + t]-mz;
        A00 += cx*cx; A01 += cx*cy; A02 += cx*cz;
        A11 += cy*cy; A12 += cy*cz; A22 += cz*cz;
    }
    A00*=0.5f; A01*=0.5f; A02*=0.5f; A11*=0.5f; A12*=0.5f; A22*=0.5f;

    float d[3];
    float V[3][3];
    ssyevd3(A00, A01, A02, A11, A12, A22, d, V);

    float nx  = V[0][0], ny  = V[1][0], nz  = V[2][0];
    float t1x = V[0][1], t1y = V[1][1], t1z = V[2][1];
    float t2x = V[0][2], t2y = V[1][2], t2z = V[2][2];
    float det = nx*(t1y*t2z - t1z*t2y)
              - ny*(t1x*t2z - t1z*t2x)
              + nz*(t1x*t2y - t1y*t2x);
    t1x *= det; t1y *= det; t1z *= det;
    g_nrm[3*i+0]=nx;  g_nrm[3*i+1]=ny;  g_nrm[3*i+2]=nz;
    g_t1 [3*i+0]=t1x; g_t1 [3*i+1]=t1y; g_t1 [3*i+2]=t1z;
    g_t2 [3*i+0]=t2x; g_t2 [3*i+1]=t2y; g_t2 [3*i+2]=t2z;
    float px = pts[3*i+0], py = pts[3*i+1], pz = pts[3*i+2];
    float bminx = INFINITY, bminy = INFINITY, bmaxx = -INFINITY, bmaxy = -INFINITY;
    for (int r = 0; r < KK; r++) {
        float dx = sp[(3*r+0)*32 + t]-px;
        float dy = sp[(3*r+1)*32 + t]-py;
        float dz = sp[(3*r+2)*32 + t]-pz;
        float a0 = (dx*t1x + dy*t1y) + dz*t1z;
        float a1 = (dx*t2x + dy*t2y) + dz*t2z;
        g_dt[(i*KK+r)*2+0] = a0;
        g_dt[(i*KK+r)*2+1] = a1;
        bminx = fminf(bminx, a0); bmaxx = fmaxf(bmaxx, a0);
        bminy = fminf(bminy, a1); bmaxy = fmaxf(bmaxy, a1);
    }
    bminx *= 1.1f; bminy *= 1.1f; bmaxx *= 1.1f; bmaxy *= 1.1f;
    float ml = fmaxf(bmaxx - bminx, bmaxy - bminy);
    g_maxlen[i] = ml;
    for (int r = 0; r < KK; r++) {
        float a0 = g_dt[(i*KK+r)*2+0];
        float a1 = g_dt[(i*KK+r)*2+1];
        float c0 = (a0 - bminx)/ml*2.0f - 1.0f;
        float c1 = (a1 - bminy)/ml*2.0f - 1.0f;
        g_coords2[i*KK+r] = make_float2(c0, c1);
    }
}

// ---------------- stage 3: shape operator + gaussian curvature (R9 staged) ----
__global__ __launch_bounds__(32) void gauss_kernel() {
    __shared__ float sn[KK*3*32];                 // 19.2 KB
    int t = threadIdx.x;
    int i = blockIdx.x * 32 + t;
    const int* idx = g_idx + i*KK;

    #pragma unroll
    for (int r = 0; r < KK; r++) {
        int j = idx[r];
        sn[(3*r+0)*32 + t] = g_nrm[3*j+0];
        sn[(3*r+1)*32 + t] = g_nrm[3*j+1];
        sn[(3*r+2)*32 + t] = g_nrm[3*j+2];
    }

    float n0x = g_nrm[3*i+0], n0y = g_nrm[3*i+1], n0z = g_nrm[3*i+2];
    float t1x = g_t1[3*i+0],  t1y = g_t1[3*i+1],  t1z = g_t1[3*i+2];
    float t2x = g_t2[3*i+0],  t2y = g_t2[3*i+1],  t2z = g_t2[3*i+2];
    float xx=0.f, xy=0.f, yy=0.f;
    float y00=0.f, y01=0.f, y10=0.f, y11=0.f;
    for (int r = 0; r < KK; r++) {
        float lnx = sn[(3*r+0)*32 + t] - n0x;
        float lny = sn[(3*r+1)*32 + t] - n0y;
        float lnz = sn[(3*r+2)*32 + t] - n0z;
        float dn0 = (lnx*t1x + lny*t1y) + lnz*t1z;
        float dn1 = (lnx*t2x + lny*t2y) + lnz*t2z;
        float dt0 = g_dt[(i*KK+r)*2+0];
        float dt1 = g_dt[(i*KK+r)*2+1];
        xx += dt0*dt0; xy += dt0*dt1; yy += dt1*dt1;
        y00 += dn0*dt0; y01 += dn0*dt1;
        y10 += dn1*dt0; y11 += dn1*dt1;
    }
    float S00 = y00 + y00, S01 = y01 + y10, S11 = y11 + y11;
    float tr = xx + yy, df = xx - yy;
    float disc = sqrtf(df*df + 4.0f*xy*xy);
    float a = 0.5f*(tr - disc), b = 0.5f*(tr + disc);
    float vx = xy, vy = b - xx;
    float nn = sqrtf(vx*vx + vy*vy);
    if (nn > 0.0f) { vx /= nn; vy /= nn; }
    else           { vx = 1.0f; vy = 0.0f; }
    float q00 = vy, q10 = -vx, q01 = vx, q11 = vy;
    float sq00 = S00*q00 + S01*q10, sq01 = S00*q01 + S01*q11;
    float sq10 = S01*q00 + S11*q10, sq11 = S01*q01 + S11*q11;
    float m00 = q00*sq00 + q10*sq10;
    float m01 = q00*sq01 + q10*sq11;
    float m10 = q01*sq00 + q11*sq10;
    float m11 = q01*sq01 + q11*sq11;
    float E00 = m00 / (2.0f*a  + 1e-8f);
    float E01 = m01 / ((a + b) + 1e-8f);
    float E10 = m10 / ((a + b) + 1e-8f);
    float E11 = m11 / (2.0f*b  + 1e-8f);
    float u00 = q00*E00 + q01*E10, u01 = q00*E01 + q01*E11;
    float u10 = q10*E00 + q11*E10, u11 = q10*E01 + q11*E11;
    float w00 = u00*q00 + u01*q01;
    float w01 = u00*q10 + u01*q11;
    float w10 = u10*q00 + u11*q01;
    float w11 = u10*q10 + u11*q11;
    g_gauss[i] = w00*w11 - w01*w10;
}

// ---------------- stage 4: Voronoi (R14: R6 body + sure-lose tile gate) ------
// Thread 0 folds this point's contribution with the IDENTICAL float
// expressions the original final_kernel used -> final's accumulation sees
// identical values in identical order -> bit-identical output.
__global__ __launch_bounds__(128) void voronoi_kernel() {
    __shared__ float2 ss[KK];
    __shared__ int    sbeat[64];      // -1 = whole tile provably lost, else jstar
    __shared__ int    part[128];
    int i = blockIdx.x;
    int t = threadIdx.x;
    if (t < KK) ss[t] = g_coords2[i*KK + t];
    __syncthreads();
    const float step = 2.0f / 63.0f;

    if (t < 64) {
        int ta = t >> 3, tb = t & 7;
        float cx = -1.0f + ((float)(ta*8) + 3.5f) * step;
        float cy = -1.0f + ((float)(tb*8) + 3.5f) * step;
        float bestd = INFINITY; int bestj = 1;
        for (int j = 1; j < KK; j++) {
            float ex = cx - ss[j].x, ey = cy - ss[j].y;
            float dj = ex*ex + ey*ey;
            if (dj < bestd) { bestd = dj; bestj = j; }
        }
        float e0x = cx - ss[0].x, e0y = cy - ss[0].y;
        float d0c = e0x*e0x + e0y*e0y;
        const float rr = 4.9497475f * step;   // 8x8 tile half-diagonal
        bool sure = (sqrtf(bestd) + 2.0f*rr + 2e-3f) < sqrtf(d0c);
        sbeat[t] = sure ? -1 : bestj;
    }
    __syncthreads();

    float s0x = ss[0].x, s0y = ss[0].y;
    int cnt = 0;
    for (int c = t; c < NG; c += 128) {
        int a = c >> 6, b = c & 63;
        int jstar = sbeat[(a >> 3)*8 + (b >> 3)];
        if (jstar < 0) continue;              // whole tile provably lost
        float gx = -1.0f + (float)a * step;
        float gy = -1.0f + (float)b * step;
        float dx = gx - s0x, dy = gy - s0y;
        float d0 = dx*dx + dy*dy;
        float2 sj = ss[jstar];
        float ex = gx - sj.x, ey = gy - sj.y;
        float djs = ex*ex + ey*ey;
        bool lost = djs < d0;
        if (!lost) {
            for (int j = 1; j < KK; j++) {
                float2 s = ss[j];
                float fx = gx - s.x, fy = gy - s.y;
                float dj = fx*fx + fy*fy;
                if (dj < d0) { lost = true; break; }
            }
        }
        cnt += lost ? 0 : 1;
    }
    part[t] = cnt;
    __syncthreads();
    for (int s = 64; s > 0; s >>= 1) {
        if (t < s) part[t] += part[t+s];
        __syncthreads();
    }
    if (t == 0) {
        float ml = g_maxlen[i];
        float area = (float)part[0] * (ml*ml) / 3969.0f;   // EXACT final expr
        g_contrib[i] = (double)(g_gauss[i] * area);        // EXACT final expr
    }
}

// ---------------- stage 5: final reduction (contrib pre-folded) ---------------
__global__ __launch_bounds__(1024) void final_kernel(float* __restrict__ out) {
    __shared__ double sh[1024];
    int t = threadIdx.x;
    double acc = 0.0;
    for (int i = t; i < N; i += 1024) {
        acc += g_contrib[i];
    }
    sh[t] = acc;
    __syncthreads();
    for (int s = 512; s > 0; s >>= 1) {
        if (t < s) sh[t] += sh[t+s];
        __syncthreads();
    }
    if (t == 0) {
        float v = (float)sh[0];
        v = v / 2.0f;
        v = v / 3.14159274101257324f;
        out[0] = v;
    }
}

// ---------------- launch ------------------------------------------------------
extern "C" void kernel_launch(void* const* d_in, const int* in_sizes, int n_in,
                              void* d_out, int out_size) {
    const float* pts = (const float*)d_in[0];
    float* out = (float*)d_out;
    knn_q4_kernel<<<N/QB, TS>>>(pts);
    frames_kernel<<<N/32, 32>>>(pts);
    gauss_kernel <<<N/32, 32>>>();
    voronoi_kernel<<<N, 128>>>();
    final_kernel <<<1, 1024>>>(out);
}